// round 12
// baseline (speedup 1.0000x reference)
#include <cuda_runtime.h>
#include <cuda_bf16.h>
#include <cuda_fp8.h>
#include <math.h>
#include <stdint.h>

// Problem constants
#define BATCH 64
#define NP 24
#define NPAT 576
#define DH 768
#define KDIM 768
#define LLAT 1024
#define HW 384
#define PSZ 16
#define TAU_INV 2.0f
#define EPSN 1e-8f
#define MTOT (BATCH*NPAT) // 36864
#define FP8_SCALE 64.0f
#define SCL8 (TAU_INV / (FP8_SCALE * FP8_SCALE))

// Unified tiling: 128x128 block tile, 8 warps of 32x64, 256 threads, 2-stage
#define BM 128
#define BN 128
#define NTHR 256
// bf16 (embed): BK=64 elems, 144-B padded rows
#define BKC 64
#define BKP 72
#define ASTG (BM * BKP * 2)    // 18432 B
#define BSTG (BN * BKP * 2)    // 18432 B
// fp8 (far/close): BK=128 elems, 144-B padded rows
#define BKP8 144
#define ASTG8 (BM * BKP8)      // 18432 B
#define BSTG8 (BN * BKP8)      // 18432 B
#define NK8 (DH / 128)         // 6
#define SMEM_DYN (2 * (ASTG + BSTG))  // 73728 B (same for both paths)

// Scratch
__device__ __nv_bfloat16 g_Ah[(size_t)MTOT * KDIM];
__device__ __nv_bfloat16 g_Wh[(size_t)DH * KDIM];
__device__ __nv_bfloat16 g_pne[(size_t)MTOT * DH];
__device__ uint8_t g_pn8[(size_t)(MTOT + 128) * DH];   // +pad rows (stay zero)
__device__ uint8_t g_ln8[(size_t)LLAT * DH];
__device__ double g_far[BATCH];
__device__ double g_close[BATCH];

// far upper-triangle 128-tiles over 5x5 (tJ >= tI)
__constant__ int c_TI5[15] = {0,0,0,0,0, 1,1,1,1, 2,2,2, 3,3, 4};
__constant__ int c_TJ5[15] = {0,1,2,3,4, 1,2,3,4, 2,3,4, 3,4, 4};

// ---------------------------------------------------------------- PTX helpers
__device__ __forceinline__ void mma16816(float c[4],
    uint32_t a0, uint32_t a1, uint32_t a2, uint32_t a3,
    uint32_t b0, uint32_t b1)
{
    asm volatile(
        "mma.sync.aligned.m16n8k16.row.col.f32.bf16.bf16.f32 "
        "{%0,%1,%2,%3}, {%4,%5,%6,%7}, {%8,%9}, {%0,%1,%2,%3};\n"
        : "+f"(c[0]), "+f"(c[1]), "+f"(c[2]), "+f"(c[3])
        : "r"(a0), "r"(a1), "r"(a2), "r"(a3), "r"(b0), "r"(b1));
}
__device__ __forceinline__ void mma16832q(float c[4],
    uint32_t a0, uint32_t a1, uint32_t a2, uint32_t a3,
    uint32_t b0, uint32_t b1)
{
    asm volatile(
        "mma.sync.aligned.m16n8k32.row.col.f32.e4m3.e4m3.f32 "
        "{%0,%1,%2,%3}, {%4,%5,%6,%7}, {%8,%9}, {%0,%1,%2,%3};\n"
        : "+f"(c[0]), "+f"(c[1]), "+f"(c[2]), "+f"(c[3])
        : "r"(a0), "r"(a1), "r"(a2), "r"(a3), "r"(b0), "r"(b1));
}
__device__ __forceinline__ void cpa16(uint32_t dst, const void* src) {
    asm volatile("cp.async.cg.shared.global [%0], [%1], 16;\n" :: "r"(dst), "l"(src));
}
__device__ __forceinline__ void cp_commit() { asm volatile("cp.async.commit_group;\n"); }
__device__ __forceinline__ void cp_wait0()  { asm volatile("cp.async.wait_group 0;\n"); }
__device__ __forceinline__ void cp_wait1()  { asm volatile("cp.async.wait_group 1;\n"); }
__device__ __forceinline__ void ldsm4(uint32_t& r0, uint32_t& r1, uint32_t& r2, uint32_t& r3,
                                      uint32_t addr)
{
    asm volatile("ldmatrix.sync.aligned.m8n8.x4.shared.b16 {%0,%1,%2,%3}, [%4];\n"
                 : "=r"(r0), "=r"(r1), "=r"(r2), "=r"(r3) : "r"(addr));
}

// ================================================================ bf16 path (embed)
__device__ __forceinline__ void load_stage(uint32_t sAu, uint32_t sBu, int stage,
    const __nv_bfloat16* aG, const __nv_bfloat16* bG, int k0, int tid)
{
    uint32_t aBase = sAu + (uint32_t)stage * ASTG;
    uint32_t bBase = sBu + (uint32_t)stage * BSTG;
    #pragma unroll
    for (int it = 0; it < 4; it++) {
        int idx = tid + it * NTHR;          // 0..1023
        int row = idx >> 3, slot = idx & 7;
        cpa16(aBase + (uint32_t)(row * BKP + slot * 8) * 2,
              aG + (size_t)row * KDIM + k0 + slot * 8);
        cpa16(bBase + (uint32_t)(row * BKP + slot * 8) * 2,
              bG + (size_t)row * KDIM + k0 + slot * 8);
    }
}

__device__ __forceinline__ void mainloop(
    const __nv_bfloat16* __restrict__ aG, const __nv_bfloat16* __restrict__ bG,
    uint32_t sAu, uint32_t sBu, float acc[2][8][4])
{
    int tid  = threadIdx.x;
    int lane = tid & 31, warp = tid >> 5;
    int wm = (warp >> 1) * 32;      // 0,32,64,96
    int wn = (warp & 1) * 64;       // 0,64
    int arow  = lane & 15;
    int acol8 = (lane >> 4) * 8;
    int bn  = ((lane >> 4) & 1) * 8 + (lane & 7);
    int bk8 = ((lane >> 3) & 1) * 8;

    uint32_t aAddr[2], bAddr[4];
    #pragma unroll
    for (int mi = 0; mi < 2; mi++)
        aAddr[mi] = sAu + (uint32_t)((wm + mi * 16 + arow) * BKP + acol8) * 2;
    #pragma unroll
    for (int p = 0; p < 4; p++)
        bAddr[p] = sBu + (uint32_t)((wn + p * 16 + bn) * BKP + bk8) * 2;

    load_stage(sAu, sBu, 0, aG, bG, 0, tid);   cp_commit();
    load_stage(sAu, sBu, 1, aG, bG, BKC, tid); cp_commit();

    const int nk = KDIM / BKC;  // 12
    for (int kc = 0; kc < nk; kc++) {
        int buf = kc & 1;
        if (kc == nk - 1) cp_wait0(); else cp_wait1();
        __syncthreads();
        uint32_t aoff = (uint32_t)buf * ASTG;
        uint32_t boff = (uint32_t)buf * BSTG;
        #pragma unroll
        for (int ks = 0; ks < 4; ks++) {
            uint32_t ko2 = (uint32_t)ks * 32;
            uint32_t a[2][4], b[8][2];
            #pragma unroll
            for (int mi = 0; mi < 2; mi++)
                ldsm4(a[mi][0], a[mi][1], a[mi][2], a[mi][3], aAddr[mi] + aoff + ko2);
            #pragma unroll
            for (int p = 0; p < 4; p++)
                ldsm4(b[p*2][0], b[p*2][1], b[p*2+1][0], b[p*2+1][1], bAddr[p] + boff + ko2);
            #pragma unroll
            for (int mi = 0; mi < 2; mi++)
                #pragma unroll
                for (int nj = 0; nj < 8; nj++)
                    mma16816(acc[mi][nj], a[mi][0], a[mi][1], a[mi][2], a[mi][3],
                             b[nj][0], b[nj][1]);
        }
        __syncthreads();
        if (kc + 2 < nk) {
            load_stage(sAu, sBu, buf, aG, bG, (kc + 2) * BKC, tid);
            cp_commit();
        }
    }
}

// ================================================================ fp8 path (far/close)
__device__ __forceinline__ void load_stage8(uint32_t sAu, uint32_t sBu, int stage,
    const uint8_t* aG, const uint8_t* bG, int k0, int tid)
{
    uint32_t aBase = sAu + (uint32_t)stage * ASTG8;
    uint32_t bBase = sBu + (uint32_t)stage * BSTG8;
    #pragma unroll
    for (int it = 0; it < 4; it++) {
        int idx = tid + it * NTHR;          // 0..1023
        int row = idx >> 3, slot = idx & 7;
        cpa16(aBase + (uint32_t)(row * BKP8 + slot * 16),
              aG + (size_t)row * DH + k0 + slot * 16);
        cpa16(bBase + (uint32_t)(row * BKP8 + slot * 16),
              bG + (size_t)row * DH + k0 + slot * 16);
    }
}

__device__ __forceinline__ void mainloop8(
    const uint8_t* __restrict__ aG, const uint8_t* __restrict__ bG,
    uint32_t sAu, uint32_t sBu, float acc[2][8][4])
{
    int tid  = threadIdx.x;
    int lane = tid & 31, warp = tid >> 5;
    int wm = (warp >> 1) * 32;
    int wn = (warp & 1) * 64;
    int arow  = lane & 15;
    int acolB = (lane >> 4) * 16;
    int bn  = ((lane >> 4) & 1) * 8 + (lane & 7);
    int bkB = ((lane >> 3) & 1) * 16;

    uint32_t aAddr[2], bAddr[4];
    #pragma unroll
    for (int mi = 0; mi < 2; mi++)
        aAddr[mi] = sAu + (uint32_t)((wm + mi * 16 + arow) * BKP8 + acolB);
    #pragma unroll
    for (int p = 0; p < 4; p++)
        bAddr[p] = sBu + (uint32_t)((wn + p * 16 + bn) * BKP8 + bkB);

    load_stage8(sAu, sBu, 0, aG, bG, 0, tid);   cp_commit();
    load_stage8(sAu, sBu, 1, aG, bG, 128, tid); cp_commit();

    for (int kc = 0; kc < NK8; kc++) {
        int buf = kc & 1;
        if (kc == NK8 - 1) cp_wait0(); else cp_wait1();
        __syncthreads();
        uint32_t aoff = (uint32_t)buf * ASTG8;
        uint32_t boff = (uint32_t)buf * BSTG8;
        #pragma unroll
        for (int ks = 0; ks < 4; ks++) {
            uint32_t ko = (uint32_t)ks * 32;
            uint32_t a[2][4], b[8][2];
            #pragma unroll
            for (int mi = 0; mi < 2; mi++)
                ldsm4(a[mi][0], a[mi][1], a[mi][2], a[mi][3], aAddr[mi] + aoff + ko);
            #pragma unroll
            for (int p = 0; p < 4; p++)
                ldsm4(b[p*2][0], b[p*2][1], b[p*2+1][0], b[p*2+1][1], bAddr[p] + boff + ko);
            #pragma unroll
            for (int mi = 0; mi < 2; mi++)
                #pragma unroll
                for (int nj = 0; nj < 8; nj++)
                    mma16832q(acc[mi][nj], a[mi][0], a[mi][1], a[mi][2], a[mi][3],
                              b[nj][0], b[nj][1]);
        }
        __syncthreads();
        if (kc + 2 < NK8) {
            load_stage8(sAu, sBu, buf, aG, bG, (kc + 2) * 128, tid);
            cp_commit();
        }
    }
}

// block reduce (256 threads) -> double atomic
__device__ __forceinline__ void block_reduce_add(float part, float* red, double* gout) {
    int tid = threadIdx.x, lane = tid & 31, warp = tid >> 5;
    #pragma unroll
    for (int o = 16; o; o >>= 1) part += __shfl_xor_sync(0xffffffffu, part, o);
    if (lane == 0) red[warp] = part;
    __syncthreads();
    if (tid == 0) {
        float s = 0.f;
        #pragma unroll
        for (int w = 0; w < 8; w++) s += red[w];
        atomicAdd(gout, (double)s);
    }
}

// ---------------------------------------------------------------- init
__global__ void init_k() {
    int t = threadIdx.x;
    if (t < BATCH) { g_far[t] = 0.0; g_close[t] = 0.0; }
}

// ---------------------------------------------------------------- im2col -> bf16
__global__ void im2col_k(const float* __restrict__ x) {
    int idx = blockIdx.x * 256 + threadIdx.x;
    int kq  = idx % (KDIM / 8);
    int row = idx / (KDIM / 8);
    int k  = kq * 8;
    int kw = k & 15, kh = (k >> 4) & 15, c = k >> 8;
    int pw = row % NP; int t = row / NP; int ph = t % NP; int b = t / NP;
    const float* src = x + ((size_t)(b*3 + c)*HW + ph*PSZ + kh)*HW + pw*PSZ + kw;
    float4 v0 = *(const float4*)(src);
    float4 v1 = *(const float4*)(src + 4);
    __nv_bfloat16 o[8];
    o[0]=__float2bfloat16_rn(v0.x); o[1]=__float2bfloat16_rn(v0.y);
    o[2]=__float2bfloat16_rn(v0.z); o[3]=__float2bfloat16_rn(v0.w);
    o[4]=__float2bfloat16_rn(v1.x); o[5]=__float2bfloat16_rn(v1.y);
    o[6]=__float2bfloat16_rn(v1.z); o[7]=__float2bfloat16_rn(v1.w);
    *(int4*)(g_Ah + (size_t)row * KDIM + k) = *(int4*)o;
}

// ---------------------------------------------------------------- W -> bf16
__global__ void wconv_k(const float* __restrict__ W) {
    int idx = blockIdx.x * 256 + threadIdx.x;
    const float4* src = (const float4*)(W + (size_t)idx * 8);
    float4 v0 = src[0], v1 = src[1];
    __nv_bfloat16 o[8];
    o[0]=__float2bfloat16_rn(v0.x); o[1]=__float2bfloat16_rn(v0.y);
    o[2]=__float2bfloat16_rn(v0.z); o[3]=__float2bfloat16_rn(v0.w);
    o[4]=__float2bfloat16_rn(v1.x); o[5]=__float2bfloat16_rn(v1.y);
    o[6]=__float2bfloat16_rn(v1.z); o[7]=__float2bfloat16_rn(v1.w);
    *(int4*)(g_Wh + (size_t)idx * 8) = *(int4*)o;
}

// ---------------------------------------------------------------- GEMM embed (bf16)
__global__ __launch_bounds__(NTHR, 2) void gemm_embed_k(const float* __restrict__ bias) {
    extern __shared__ __align__(16) char dsm[];
    uint32_t sAu = (uint32_t)__cvta_generic_to_shared(dsm);
    uint32_t sBu = sAu + 2u * ASTG;
    const __nv_bfloat16* aG = g_Ah + (size_t)blockIdx.x * BM * KDIM;
    const __nv_bfloat16* bG = g_Wh + (size_t)blockIdx.y * BN * KDIM;
    float acc[2][8][4] = {};
    mainloop(aG, bG, sAu, sBu, acc);

    int lane = threadIdx.x & 31, warp = threadIdx.x >> 5;
    int wm = (warp >> 1) * 32, wn = (warp & 1) * 64;
    int g = lane >> 2, lt = lane & 3;
    int rowB = blockIdx.x * BM + wm;
    int colB = blockIdx.y * BN + wn;
    #pragma unroll
    for (int mi = 0; mi < 2; mi++)
        #pragma unroll
        for (int nj = 0; nj < 8; nj++) {
            int col = colB + nj * 8 + lt * 2;
            float b0 = bias[col], b1 = bias[col + 1];
            int r0 = rowB + mi * 16 + g;
            __nv_bfloat16 p0[2] = { __float2bfloat16_rn(acc[mi][nj][0] + b0),
                                    __float2bfloat16_rn(acc[mi][nj][1] + b1) };
            __nv_bfloat16 p1[2] = { __float2bfloat16_rn(acc[mi][nj][2] + b0),
                                    __float2bfloat16_rn(acc[mi][nj][3] + b1) };
            *(uint32_t*)(g_pne + (size_t)r0 * DH + col)       = *(uint32_t*)p0;
            *(uint32_t*)(g_pne + (size_t)(r0 + 8) * DH + col) = *(uint32_t*)p1;
        }
}

// ---------------------------------------------------------------- L2 normalize -> fp8*64
__global__ void norm_patch_k() {
    int gw = (blockIdx.x * blockDim.x + threadIdx.x) >> 5;
    int lane = threadIdx.x & 31;
    if (gw >= MTOT) return;
    const ushort4* src = (const ushort4*)(g_pne + (size_t)gw * DH);
    uint32_t* dst = (uint32_t*)(g_pn8 + (size_t)gw * DH);
    float s = 0.f;
    float f[24];
    #pragma unroll
    for (int i = 0; i < 6; i++) {
        ushort4 v = src[lane + 32*i];
        f[i*4+0] = __bfloat162float(*(const __nv_bfloat16*)&v.x);
        f[i*4+1] = __bfloat162float(*(const __nv_bfloat16*)&v.y);
        f[i*4+2] = __bfloat162float(*(const __nv_bfloat16*)&v.z);
        f[i*4+3] = __bfloat162float(*(const __nv_bfloat16*)&v.w);
        s += f[i*4]*f[i*4] + f[i*4+1]*f[i*4+1] + f[i*4+2]*f[i*4+2] + f[i*4+3]*f[i*4+3];
    }
    #pragma unroll
    for (int o = 16; o; o >>= 1) s += __shfl_xor_sync(0xffffffffu, s, o);
    float inv = FP8_SCALE / fmaxf(sqrtf(s), EPSN);
    #pragma unroll
    for (int i = 0; i < 6; i++) {
        uint32_t w = 0;
        #pragma unroll
        for (int j = 0; j < 4; j++)
            w |= (uint32_t)__nv_cvt_float_to_fp8(f[i*4+j] * inv, __NV_SATFINITE, __NV_E4M3) << (8*j);
        dst[lane + 32*i] = w;
    }
}

__global__ void norm_latent_k(const float* __restrict__ latent) {
    int gw = (blockIdx.x * blockDim.x + threadIdx.x) >> 5;
    int lane = threadIdx.x & 31;
    if (gw >= LLAT) return;
    const float4* src = (const float4*)(latent + (size_t)gw * DH);
    uint32_t* dst = (uint32_t*)(g_ln8 + (size_t)gw * DH);
    float s = 0.f; float4 v[6];
    #pragma unroll
    for (int i = 0; i < 6; i++) {
        v[i] = src[lane + 32*i];
        s += v[i].x*v[i].x + v[i].y*v[i].y + v[i].z*v[i].z + v[i].w*v[i].w;
    }
    #pragma unroll
    for (int o = 16; o; o >>= 1) s += __shfl_xor_sync(0xffffffffu, s, o);
    float inv = FP8_SCALE / fmaxf(sqrtf(s), EPSN);
    #pragma unroll
    for (int i = 0; i < 6; i++) {
        float f4[4] = { v[i].x * inv, v[i].y * inv, v[i].z * inv, v[i].w * inv };
        uint32_t w = 0;
        #pragma unroll
        for (int j = 0; j < 4; j++)
            w |= (uint32_t)__nv_cvt_float_to_fp8(f4[j], __NV_SATFINITE, __NV_E4M3) << (8*j);
        dst[lane + 32*i] = w;
    }
}

// ---------------------------------------------------------------- far (fp8)
// 15 upper-triangle 128x128 tiles/batch, uniform strict c>r mask (weight 2)
__global__ __launch_bounds__(NTHR, 2) void far_k() {
    int t = blockIdx.x, b = blockIdx.z;
    int tI = c_TI5[t], tJ = c_TJ5[t];
    extern __shared__ __align__(16) char dsm[];
    __shared__ float red[8];
    uint32_t sAu = (uint32_t)__cvta_generic_to_shared(dsm);
    uint32_t sBu = sAu + 2u * ASTG8;
    const uint8_t* aG = g_pn8 + ((size_t)b * NPAT + tI * BM) * DH;
    const uint8_t* bG = g_pn8 + ((size_t)b * NPAT + tJ * BN) * DH;
    float acc[2][8][4] = {};
    mainloop8(aG, bG, sAu, sBu, acc);

    int lane = threadIdx.x & 31, warp = threadIdx.x >> 5;
    int wm = (warp >> 1) * 32, wn = (warp & 1) * 64;
    int g = lane >> 2, lt = lane & 3;
    float part = 0.f;
    #pragma unroll
    for (int mi = 0; mi < 2; mi++)
        #pragma unroll
        for (int nj = 0; nj < 8; nj++) {
            int r0 = tI * BM + wm + mi * 16 + g;
            int c0 = tJ * BN + wn + nj * 8 + lt * 2;
            float e0 = __expf(acc[mi][nj][0] * SCL8);
            float e1 = __expf(acc[mi][nj][1] * SCL8);
            float e2 = __expf(acc[mi][nj][2] * SCL8);
            float e3 = __expf(acc[mi][nj][3] * SCL8);
            bool vr0 = r0 < NPAT, vr1 = (r0 + 8) < NPAT;
            part += (vr0 && c0     > r0     && c0     < NPAT) ? 2.f * e0 : 0.f;
            part += (vr0 && c0 + 1 > r0     && c0 + 1 < NPAT) ? 2.f * e1 : 0.f;
            part += (vr1 && c0     > r0 + 8 && c0     < NPAT) ? 2.f * e2 : 0.f;
            part += (vr1 && c0 + 1 > r0 + 8 && c0 + 1 < NPAT) ? 2.f * e3 : 0.f;
        }
    block_reduce_add(part, red, &g_far[b]);
}

// ---------------------------------------------------------------- close (fp8)
// 36864 x 1024; 128-row tiles may straddle one batch boundary
__global__ __launch_bounds__(NTHR, 2) void close_k() {
    extern __shared__ __align__(16) char dsm[];
    __shared__ float red[8];
    uint32_t sAu = (uint32_t)__cvta_generic_to_shared(dsm);
    uint32_t sBu = sAu + 2u * ASTG8;
    const uint8_t* aG = g_pn8 + (size_t)blockIdx.x * BM * DH;
    const uint8_t* bG = g_ln8 + (size_t)blockIdx.y * BN * DH;
    float acc[2][8][4] = {};
    mainloop8(aG, bG, sAu, sBu, acc);

    int lane = threadIdx.x & 31, warp = threadIdx.x >> 5;
    int wm = (warp >> 1) * 32;
    int g = lane >> 2;
    int r0t = blockIdx.x * BM;
    int b_lo = r0t / NPAT;
    int bound = (b_lo + 1) * NPAT;
    float plo = 0.f, phi = 0.f;
    #pragma unroll
    for (int mi = 0; mi < 2; mi++) {
        int gr0 = r0t + wm + mi * 16 + g;
        float s0 = 0.f, s1 = 0.f;
        #pragma unroll
        for (int nj = 0; nj < 8; nj++) {
            s0 += __expf(acc[mi][nj][0] * SCL8) + __expf(acc[mi][nj][1] * SCL8);
            s1 += __expf(acc[mi][nj][2] * SCL8) + __expf(acc[mi][nj][3] * SCL8);
        }
        if (gr0 < bound)     plo += s0; else phi += s0;
        if (gr0 + 8 < bound) plo += s1; else phi += s1;
    }
    block_reduce_add(plo, red, &g_close[b_lo]);
    __syncthreads();
    if (b_lo + 1 < BATCH) block_reduce_add(phi, red, &g_close[b_lo + 1]);
}

// ---------------------------------------------------------------- finish
__global__ void finish_k(float* out) {
    __shared__ double sh[BATCH];
    int t = threadIdx.x;
    sh[t] = log(g_far[t]) - log(g_close[t]);
    __syncthreads();
    if (t == 0) {
        double s = 0.0;
        for (int i = 0; i < BATCH; i++) s += sh[i];
        out[0] = (float)(s / (double)BATCH);
    }
}

// ---------------------------------------------------------------- launch
extern "C" void kernel_launch(void* const* d_in, const int* in_sizes, int n_in,
                              void* d_out, int out_size) {
    const float* x      = (const float*)d_in[0];
    const float* conv_w = (const float*)d_in[1];
    const float* conv_b = (const float*)d_in[2];
    const float* latent = (const float*)d_in[3];
    float* out = (float*)d_out;

    cudaFuncSetAttribute(gemm_embed_k, cudaFuncAttributeMaxDynamicSharedMemorySize, SMEM_DYN);
    cudaFuncSetAttribute(far_k,        cudaFuncAttributeMaxDynamicSharedMemorySize, SMEM_DYN);
    cudaFuncSetAttribute(close_k,      cudaFuncAttributeMaxDynamicSharedMemorySize, SMEM_DYN);

    init_k<<<1, 64>>>();
    im2col_k<<<(MTOT * (KDIM / 8)) / 256, 256>>>(x);
    wconv_k<<<(DH * KDIM / 8) / 256, 256>>>(conv_w);
    gemm_embed_k<<<dim3(MTOT / BM, DH / BN), NTHR, SMEM_DYN>>>(conv_b);
    norm_patch_k<<<(MTOT * 32) / 256, 256>>>();
    norm_latent_k<<<(LLAT * 32) / 256, 256>>>(latent);
    far_k<<<dim3(15, 1, BATCH), NTHR, SMEM_DYN>>>();
    close_k<<<dim3(MTOT / BM, LLAT / BN), NTHR, SMEM_DYN>>>();
    finish_k<<<1, BATCH>>>(out);
}

// round 13
// speedup vs baseline: 1.5649x; 1.5649x over previous
#include <cuda_runtime.h>
#include <cuda_bf16.h>
#include <cuda_fp8.h>
#include <math.h>
#include <stdint.h>

// Problem constants
#define BATCH 64
#define NP 24
#define NPAT 576
#define DH 768
#define KDIM 768
#define LLAT 1024
#define HW 384
#define PSZ 16
#define TAU_INV 2.0f
#define EPSN 1e-8f
#define MTOT (BATCH*NPAT) // 36864
#define FP8_SCALE 64.0f
#define SCL8 (TAU_INV / (FP8_SCALE * FP8_SCALE))

// bf16 GEMM tiling (embed): 64x128 tile, 4 warps of 32x64, BK=64, 2-stage
#define BM 64
#define BN 128
#define BKC 64
#define BKP 72
#define NTHR 128
#define ASTG (BM * BKP * 2)   // 9216 B
#define BSTG (BN * BKP * 2)   // 18432 B
#define SMEM_DYN (2 * (ASTG + BSTG))  // 55296 B

// fp8 GEMM tiling (pair): same tile, K chunks of 128 fp8
#define BKP8 144
#define ASTG8 (BM * BKP8)     // 9216 B
#define BSTG8 (BN * BKP8)     // 18432 B
#define NK8 (DH / 128)        // 6

// merged-kernel block bookkeeping
#define IM2COL_BLOCKS (MTOT * (KDIM / 8) / 256)   // 13824
#define WCONV_BLOCKS  ((DH * KDIM / 8) / 256)     // 288
#define FAR_CTAS      (29 * BATCH)                // 1856
#define CLOSE_CTAS    ((MTOT / BM) * (LLAT / BN)) // 4608

// Scratch
__device__ __nv_bfloat16 g_Ah[(size_t)MTOT * KDIM];
__device__ __nv_bfloat16 g_Wh[(size_t)DH * KDIM];
__device__ __nv_bfloat16 g_pne[(size_t)MTOT * DH];
__device__ uint8_t g_pn8[(size_t)(MTOT + 128) * DH];   // +pad rows (stay zero)
__device__ uint8_t g_ln8[(size_t)LLAT * DH];
__device__ double g_far[BATCH];
__device__ double g_close[BATCH];

// far triangle tile list: 64-row tiles (9) x 128-col tiles (5), tiles containing c>r
__constant__ int c_TI[29] = {0,0,0,0,0, 1,1,1,1,1, 2,2,2,2, 3,3,3,3, 4,4,4, 5,5,5, 6,6, 7,7, 8};
__constant__ int c_TJ[29] = {0,1,2,3,4, 0,1,2,3,4, 1,2,3,4, 1,2,3,4, 2,3,4, 2,3,4, 3,4, 3,4, 4};

// ---------------------------------------------------------------- PTX helpers
__device__ __forceinline__ void mma16816(float c[4],
    uint32_t a0, uint32_t a1, uint32_t a2, uint32_t a3,
    uint32_t b0, uint32_t b1)
{
    asm volatile(
        "mma.sync.aligned.m16n8k16.row.col.f32.bf16.bf16.f32 "
        "{%0,%1,%2,%3}, {%4,%5,%6,%7}, {%8,%9}, {%0,%1,%2,%3};\n"
        : "+f"(c[0]), "+f"(c[1]), "+f"(c[2]), "+f"(c[3])
        : "r"(a0), "r"(a1), "r"(a2), "r"(a3), "r"(b0), "r"(b1));
}
__device__ __forceinline__ void mma16832q(float c[4],
    uint32_t a0, uint32_t a1, uint32_t a2, uint32_t a3,
    uint32_t b0, uint32_t b1)
{
    asm volatile(
        "mma.sync.aligned.m16n8k32.row.col.f32.e4m3.e4m3.f32 "
        "{%0,%1,%2,%3}, {%4,%5,%6,%7}, {%8,%9}, {%0,%1,%2,%3};\n"
        : "+f"(c[0]), "+f"(c[1]), "+f"(c[2]), "+f"(c[3])
        : "r"(a0), "r"(a1), "r"(a2), "r"(a3), "r"(b0), "r"(b1));
}
__device__ __forceinline__ void cpa16(uint32_t dst, const void* src) {
    asm volatile("cp.async.cg.shared.global [%0], [%1], 16;\n" :: "r"(dst), "l"(src));
}
__device__ __forceinline__ void cp_commit() { asm volatile("cp.async.commit_group;\n"); }
__device__ __forceinline__ void cp_wait0()  { asm volatile("cp.async.wait_group 0;\n"); }
__device__ __forceinline__ void cp_wait1()  { asm volatile("cp.async.wait_group 1;\n"); }
__device__ __forceinline__ void ldsm4(uint32_t& r0, uint32_t& r1, uint32_t& r2, uint32_t& r3,
                                      uint32_t addr)
{
    asm volatile("ldmatrix.sync.aligned.m8n8.x4.shared.b16 {%0,%1,%2,%3}, [%4];\n"
                 : "=r"(r0), "=r"(r1), "=r"(r2), "=r"(r3) : "r"(addr));
}

// ================================================================ bf16 path (embed)
__device__ __forceinline__ void load_stage(uint32_t sAu, uint32_t sBu, int stage,
    const __nv_bfloat16* aG, const __nv_bfloat16* bG, int k0, int tid)
{
    uint32_t aBase = sAu + (uint32_t)stage * ASTG;
    uint32_t bBase = sBu + (uint32_t)stage * BSTG;
    #pragma unroll
    for (int it = 0; it < 4; it++) {
        int idx = tid + it * NTHR;
        int row = idx >> 3, slot = idx & 7;
        cpa16(aBase + (uint32_t)(row * BKP + slot * 8) * 2,
              aG + (size_t)row * KDIM + k0 + slot * 8);
    }
    #pragma unroll
    for (int it = 0; it < 8; it++) {
        int idx = tid + it * NTHR;
        int row = idx >> 3, slot = idx & 7;
        cpa16(bBase + (uint32_t)(row * BKP + slot * 8) * 2,
              bG + (size_t)row * KDIM + k0 + slot * 8);
    }
}

__device__ __forceinline__ void mainloop(
    const __nv_bfloat16* __restrict__ aG, const __nv_bfloat16* __restrict__ bG,
    uint32_t sAu, uint32_t sBu, float acc[2][8][4])
{
    int tid  = threadIdx.x;
    int lane = tid & 31, warp = tid >> 5;
    int wm = (warp >> 1) * 32;
    int wn = (warp & 1) * 64;
    int arow  = lane & 15;
    int acol8 = (lane >> 4) * 8;
    int bn  = ((lane >> 4) & 1) * 8 + (lane & 7);
    int bk8 = ((lane >> 3) & 1) * 8;

    uint32_t aAddr[2], bAddr[4];
    #pragma unroll
    for (int mi = 0; mi < 2; mi++)
        aAddr[mi] = sAu + (uint32_t)((wm + mi * 16 + arow) * BKP + acol8) * 2;
    #pragma unroll
    for (int p = 0; p < 4; p++)
        bAddr[p] = sBu + (uint32_t)((wn + p * 16 + bn) * BKP + bk8) * 2;

    load_stage(sAu, sBu, 0, aG, bG, 0, tid);   cp_commit();
    load_stage(sAu, sBu, 1, aG, bG, BKC, tid); cp_commit();

    const int nk = KDIM / BKC;  // 12
    for (int kc = 0; kc < nk; kc++) {
        int buf = kc & 1;
        if (kc == nk - 1) cp_wait0(); else cp_wait1();
        __syncthreads();
        uint32_t aoff = (uint32_t)buf * ASTG;
        uint32_t boff = (uint32_t)buf * BSTG;
        #pragma unroll
        for (int ks = 0; ks < 4; ks++) {
            uint32_t ko2 = (uint32_t)ks * 32;
            uint32_t a[2][4], b[8][2];
            #pragma unroll
            for (int mi = 0; mi < 2; mi++)
                ldsm4(a[mi][0], a[mi][1], a[mi][2], a[mi][3], aAddr[mi] + aoff + ko2);
            #pragma unroll
            for (int p = 0; p < 4; p++)
                ldsm4(b[p*2][0], b[p*2][1], b[p*2+1][0], b[p*2+1][1], bAddr[p] + boff + ko2);
            #pragma unroll
            for (int mi = 0; mi < 2; mi++)
                #pragma unroll
                for (int nj = 0; nj < 8; nj++)
                    mma16816(acc[mi][nj], a[mi][0], a[mi][1], a[mi][2], a[mi][3],
                             b[nj][0], b[nj][1]);
        }
        __syncthreads();
        if (kc + 2 < nk) {
            load_stage(sAu, sBu, buf, aG, bG, (kc + 2) * BKC, tid);
            cp_commit();
        }
    }
}

// ================================================================ fp8 path (pair)
__device__ __forceinline__ void load_stage8(uint32_t sAu, uint32_t sBu, int stage,
    const uint8_t* aG, const uint8_t* bG, int k0, int tid)
{
    uint32_t aBase = sAu + (uint32_t)stage * ASTG8;
    uint32_t bBase = sBu + (uint32_t)stage * BSTG8;
    #pragma unroll
    for (int it = 0; it < 4; it++) {
        int idx = tid + it * NTHR;
        int row = idx >> 3, slot = idx & 7;
        cpa16(aBase + (uint32_t)(row * BKP8 + slot * 16),
              aG + (size_t)row * DH + k0 + slot * 16);
    }
    #pragma unroll
    for (int it = 0; it < 8; it++) {
        int idx = tid + it * NTHR;
        int row = idx >> 3, slot = idx & 7;
        cpa16(bBase + (uint32_t)(row * BKP8 + slot * 16),
              bG + (size_t)row * DH + k0 + slot * 16);
    }
}

__device__ __forceinline__ void mainloop8(
    const uint8_t* __restrict__ aG, const uint8_t* __restrict__ bG,
    uint32_t sAu, uint32_t sBu, float acc[2][8][4])
{
    int tid  = threadIdx.x;
    int lane = tid & 31, warp = tid >> 5;
    int wm = (warp >> 1) * 32;
    int wn = (warp & 1) * 64;
    int arow  = lane & 15;
    int acolB = (lane >> 4) * 16;
    int bn  = ((lane >> 4) & 1) * 8 + (lane & 7);
    int bkB = ((lane >> 3) & 1) * 16;

    uint32_t aAddr[2], bAddr[4];
    #pragma unroll
    for (int mi = 0; mi < 2; mi++)
        aAddr[mi] = sAu + (uint32_t)((wm + mi * 16 + arow) * BKP8 + acolB);
    #pragma unroll
    for (int p = 0; p < 4; p++)
        bAddr[p] = sBu + (uint32_t)((wn + p * 16 + bn) * BKP8 + bkB);

    load_stage8(sAu, sBu, 0, aG, bG, 0, tid);   cp_commit();
    load_stage8(sAu, sBu, 1, aG, bG, 128, tid); cp_commit();

    for (int kc = 0; kc < NK8; kc++) {
        int buf = kc & 1;
        if (kc == NK8 - 1) cp_wait0(); else cp_wait1();
        __syncthreads();
        uint32_t aoff = (uint32_t)buf * ASTG8;
        uint32_t boff = (uint32_t)buf * BSTG8;
        #pragma unroll
        for (int ks = 0; ks < 4; ks++) {
            uint32_t ko = (uint32_t)ks * 32;
            uint32_t a[2][4], b[8][2];
            #pragma unroll
            for (int mi = 0; mi < 2; mi++)
                ldsm4(a[mi][0], a[mi][1], a[mi][2], a[mi][3], aAddr[mi] + aoff + ko);
            #pragma unroll
            for (int p = 0; p < 4; p++)
                ldsm4(b[p*2][0], b[p*2][1], b[p*2+1][0], b[p*2+1][1], bAddr[p] + boff + ko);
            #pragma unroll
            for (int mi = 0; mi < 2; mi++)
                #pragma unroll
                for (int nj = 0; nj < 8; nj++)
                    mma16832q(acc[mi][nj], a[mi][0], a[mi][1], a[mi][2], a[mi][3],
                              b[nj][0], b[nj][1]);
        }
        __syncthreads();
        if (kc + 2 < NK8) {
            load_stage8(sAu, sBu, buf, aG, bG, (kc + 2) * 128, tid);
            cp_commit();
        }
    }
}

// block reduce (128 threads) -> double atomic
__device__ __forceinline__ void block_reduce_add(float part, float* red, double* gout) {
    int tid = threadIdx.x, lane = tid & 31, warp = tid >> 5;
    #pragma unroll
    for (int o = 16; o; o >>= 1) part += __shfl_xor_sync(0xffffffffu, part, o);
    if (lane == 0) red[warp] = part;
    __syncthreads();
    if (tid == 0) {
        float s = red[0] + red[1] + red[2] + red[3];
        atomicAdd(gout, (double)s);
    }
}

// ---------------------------------------------------------------- prep: im2col + wconv + init
__global__ void prep_k(const float* __restrict__ x, const float* __restrict__ W) {
    int bx = blockIdx.x;
    if (bx < IM2COL_BLOCKS) {
        int idx = bx * 256 + threadIdx.x;
        int kq  = idx % (KDIM / 8);
        int row = idx / (KDIM / 8);
        int k  = kq * 8;
        int kw = k & 15, kh = (k >> 4) & 15, c = k >> 8;
        int pw = row % NP; int t = row / NP; int ph = t % NP; int b = t / NP;
        const float* src = x + ((size_t)(b*3 + c)*HW + ph*PSZ + kh)*HW + pw*PSZ + kw;
        float4 v0 = *(const float4*)(src);
        float4 v1 = *(const float4*)(src + 4);
        __nv_bfloat16 o[8];
        o[0]=__float2bfloat16_rn(v0.x); o[1]=__float2bfloat16_rn(v0.y);
        o[2]=__float2bfloat16_rn(v0.z); o[3]=__float2bfloat16_rn(v0.w);
        o[4]=__float2bfloat16_rn(v1.x); o[5]=__float2bfloat16_rn(v1.y);
        o[6]=__float2bfloat16_rn(v1.z); o[7]=__float2bfloat16_rn(v1.w);
        *(int4*)(g_Ah + (size_t)row * KDIM + k) = *(int4*)o;
    } else if (bx < IM2COL_BLOCKS + WCONV_BLOCKS) {
        int idx = (bx - IM2COL_BLOCKS) * 256 + threadIdx.x;
        const float4* src = (const float4*)(W + (size_t)idx * 8);
        float4 v0 = src[0], v1 = src[1];
        __nv_bfloat16 o[8];
        o[0]=__float2bfloat16_rn(v0.x); o[1]=__float2bfloat16_rn(v0.y);
        o[2]=__float2bfloat16_rn(v0.z); o[3]=__float2bfloat16_rn(v0.w);
        o[4]=__float2bfloat16_rn(v1.x); o[5]=__float2bfloat16_rn(v1.y);
        o[6]=__float2bfloat16_rn(v1.z); o[7]=__float2bfloat16_rn(v1.w);
        *(int4*)(g_Wh + (size_t)idx * 8) = *(int4*)o;
    } else {
        int t = threadIdx.x;
        if (t < BATCH) { g_far[t] = 0.0; g_close[t] = 0.0; }
    }
}

// ---------------------------------------------------------------- GEMM embed (bf16)
__global__ __launch_bounds__(NTHR, 3) void gemm_embed_k(const float* __restrict__ bias) {
    extern __shared__ __align__(16) char dsm[];
    uint32_t sAu = (uint32_t)__cvta_generic_to_shared(dsm);
    uint32_t sBu = sAu + 2u * ASTG;
    const __nv_bfloat16* aG = g_Ah + (size_t)blockIdx.x * BM * KDIM;
    const __nv_bfloat16* bG = g_Wh + (size_t)blockIdx.y * BN * KDIM;
    float acc[2][8][4] = {};
    mainloop(aG, bG, sAu, sBu, acc);

    int lane = threadIdx.x & 31, warp = threadIdx.x >> 5;
    int wm = (warp >> 1) * 32, wn = (warp & 1) * 64;
    int g = lane >> 2, lt = lane & 3;
    int rowB = blockIdx.x * BM + wm;
    int colB = blockIdx.y * BN + wn;
    #pragma unroll
    for (int mi = 0; mi < 2; mi++)
        #pragma unroll
        for (int nj = 0; nj < 8; nj++) {
            int col = colB + nj * 8 + lt * 2;
            float b0 = bias[col], b1 = bias[col + 1];
            int r0 = rowB + mi * 16 + g;
            __nv_bfloat16 p0[2] = { __float2bfloat16_rn(acc[mi][nj][0] + b0),
                                    __float2bfloat16_rn(acc[mi][nj][1] + b1) };
            __nv_bfloat16 p1[2] = { __float2bfloat16_rn(acc[mi][nj][2] + b0),
                                    __float2bfloat16_rn(acc[mi][nj][3] + b1) };
            *(uint32_t*)(g_pne + (size_t)r0 * DH + col)       = *(uint32_t*)p0;
            *(uint32_t*)(g_pne + (size_t)(r0 + 8) * DH + col) = *(uint32_t*)p1;
        }
}

// ---------------------------------------------------------------- norm: patch + latent -> fp8*64
__global__ void norm_k(const float* __restrict__ latent) {
    int gw = (blockIdx.x * blockDim.x + threadIdx.x) >> 5;
    int lane = threadIdx.x & 31;
    if (gw < MTOT) {
        const ushort4* src = (const ushort4*)(g_pne + (size_t)gw * DH);
        uint32_t* dst = (uint32_t*)(g_pn8 + (size_t)gw * DH);
        float s = 0.f;
        float f[24];
        #pragma unroll
        for (int i = 0; i < 6; i++) {
            ushort4 v = src[lane + 32*i];
            f[i*4+0] = __bfloat162float(*(const __nv_bfloat16*)&v.x);
            f[i*4+1] = __bfloat162float(*(const __nv_bfloat16*)&v.y);
            f[i*4+2] = __bfloat162float(*(const __nv_bfloat16*)&v.z);
            f[i*4+3] = __bfloat162float(*(const __nv_bfloat16*)&v.w);
            s += f[i*4]*f[i*4] + f[i*4+1]*f[i*4+1] + f[i*4+2]*f[i*4+2] + f[i*4+3]*f[i*4+3];
        }
        #pragma unroll
        for (int o = 16; o; o >>= 1) s += __shfl_xor_sync(0xffffffffu, s, o);
        float inv = FP8_SCALE / fmaxf(sqrtf(s), EPSN);
        #pragma unroll
        for (int i = 0; i < 6; i++) {
            uint32_t w = 0;
            #pragma unroll
            for (int j = 0; j < 4; j++)
                w |= (uint32_t)__nv_cvt_float_to_fp8(f[i*4+j] * inv, __NV_SATFINITE, __NV_E4M3) << (8*j);
            dst[lane + 32*i] = w;
        }
    } else if (gw < MTOT + LLAT) {
        int r = gw - MTOT;
        const float4* src = (const float4*)(latent + (size_t)r * DH);
        uint32_t* dst = (uint32_t*)(g_ln8 + (size_t)r * DH);
        float s = 0.f; float4 v[6];
        #pragma unroll
        for (int i = 0; i < 6; i++) {
            v[i] = src[lane + 32*i];
            s += v[i].x*v[i].x + v[i].y*v[i].y + v[i].z*v[i].z + v[i].w*v[i].w;
        }
        #pragma unroll
        for (int o = 16; o; o >>= 1) s += __shfl_xor_sync(0xffffffffu, s, o);
        float inv = FP8_SCALE / fmaxf(sqrtf(s), EPSN);
        #pragma unroll
        for (int i = 0; i < 6; i++) {
            float f4[4] = { v[i].x * inv, v[i].y * inv, v[i].z * inv, v[i].w * inv };
            uint32_t w = 0;
            #pragma unroll
            for (int j = 0; j < 4; j++)
                w |= (uint32_t)__nv_cvt_float_to_fp8(f4[j], __NV_SATFINITE, __NV_E4M3) << (8*j);
            dst[lane + 32*i] = w;
        }
    }
}

// ---------------------------------------------------------------- pair: far + close fused (fp8)
__global__ __launch_bounds__(NTHR, 3) void pair_k() {
    extern __shared__ __align__(16) char dsm[];
    __shared__ float red[4];
    uint32_t sAu = (uint32_t)__cvta_generic_to_shared(dsm);
    uint32_t sBu = sAu + 2u * ASTG8;
    int t = blockIdx.x;

    if (t < FAR_CTAS) {
        // ---- far tile: triangle tiles, mask c>r (weight 2) ----
        int b  = t / 29;
        int tt = t % 29;
        int tI = c_TI[tt], tJ = c_TJ[tt];
        const uint8_t* aG = g_pn8 + ((size_t)b * NPAT + tI * BM) * DH;
        const uint8_t* bG = g_pn8 + ((size_t)b * NPAT + tJ * BN) * DH;
        float acc[2][8][4] = {};
        mainloop8(aG, bG, sAu, sBu, acc);

        int lane = threadIdx.x & 31, warp = threadIdx.x >> 5;
        int wm = (warp >> 1) * 32, wn = (warp & 1) * 64;
        int g = lane >> 2, lt = lane & 3;
        float part = 0.f;
        #pragma unroll
        for (int mi = 0; mi < 2; mi++)
            #pragma unroll
            for (int nj = 0; nj < 8; nj++) {
                int r0 = tI * BM + wm + mi * 16 + g;
                int c0 = tJ * BN + wn + nj * 8 + lt * 2;
                float e0 = __expf(acc[mi][nj][0] * SCL8);
                float e1 = __expf(acc[mi][nj][1] * SCL8);
                float e2 = __expf(acc[mi][nj][2] * SCL8);
                float e3 = __expf(acc[mi][nj][3] * SCL8);
                part += (c0     > r0     && c0     < NPAT) ? 2.f * e0 : 0.f;
                part += (c0 + 1 > r0     && c0 + 1 < NPAT) ? 2.f * e1 : 0.f;
                part += (c0     > r0 + 8 && c0     < NPAT) ? 2.f * e2 : 0.f;
                part += (c0 + 1 > r0 + 8 && c0 + 1 < NPAT) ? 2.f * e3 : 0.f;
            }
        block_reduce_add(part, red, &g_far[b]);
    } else {
        // ---- close tile: 36864 x 1024, 64-row tile in exactly one batch ----
        int idx = t - FAR_CTAS;
        int bx = idx >> 3;           // row tile (0..575)
        int by = idx & 7;            // col tile (0..7)
        const uint8_t* aG = g_pn8 + (size_t)bx * BM * DH;
        const uint8_t* bG = g_ln8 + (size_t)by * BN * DH;
        float acc[2][8][4] = {};
        mainloop8(aG, bG, sAu, sBu, acc);

        float part = 0.f;
        #pragma unroll
        for (int mi = 0; mi < 2; mi++)
            #pragma unroll
            for (int nj = 0; nj < 8; nj++) {
                part += __expf(acc[mi][nj][0] * SCL8);
                part += __expf(acc[mi][nj][1] * SCL8);
                part += __expf(acc[mi][nj][2] * SCL8);
                part += __expf(acc[mi][nj][3] * SCL8);
            }
        int b = bx / 9;              // 576 = 9 * 64
        block_reduce_add(part, red, &g_close[b]);
    }
}

// ---------------------------------------------------------------- finish
__global__ void finish_k(float* out) {
    __shared__ double sh[BATCH];
    int t = threadIdx.x;
    sh[t] = log(g_far[t]) - log(g_close[t]);
    __syncthreads();
    if (t == 0) {
        double s = 0.0;
        for (int i = 0; i < BATCH; i++) s += sh[i];
        out[0] = (float)(s / (double)BATCH);
    }
}

// ---------------------------------------------------------------- launch
extern "C" void kernel_launch(void* const* d_in, const int* in_sizes, int n_in,
                              void* d_out, int out_size) {
    const float* x      = (const float*)d_in[0];
    const float* conv_w = (const float*)d_in[1];
    const float* conv_b = (const float*)d_in[2];
    const float* latent = (const float*)d_in[3];
    float* out = (float*)d_out;

    cudaFuncSetAttribute(gemm_embed_k, cudaFuncAttributeMaxDynamicSharedMemorySize, SMEM_DYN);
    cudaFuncSetAttribute(pair_k,       cudaFuncAttributeMaxDynamicSharedMemorySize, SMEM_DYN);

    prep_k<<<IM2COL_BLOCKS + WCONV_BLOCKS + 1, 256>>>(x, conv_w);
    gemm_embed_k<<<dim3(MTOT / BM, DH / BN), NTHR, SMEM_DYN>>>(conv_b);
    norm_k<<<(MTOT + LLAT) * 32 / 256, 256>>>(latent);
    pair_k<<<FAR_CTAS + CLOSE_CTAS, NTHR, SMEM_DYN>>>();
    finish_k<<<1, BATCH>>>(out);
}